// round 6
// baseline (speedup 1.0000x reference)
#include <cuda_runtime.h>
#include <math.h>

#define B_  2
#define S_  2048
#define HID 1024
#define NH  16
#define NKV 4
#define HD  64
#define MROWS (B_*S_)   // 4096

// Scratch (no cudaMalloc allowed)
__device__ float g_Q[MROWS * HID];        // [B,S,NH,HD]
__device__ float g_K[MROWS * NKV * HD];   // [B,S,NKV,HD]
__device__ float g_V[MROWS * NKV * HD];
__device__ float g_A[MROWS * HID];        // attention output [B,S,NH,HD]

__device__ __forceinline__ unsigned f2tf32(float x) {
    unsigned r;
    asm("cvt.rna.tf32.f32 %0, %1;" : "=r"(r) : "f"(x));
    return r;
}

// ---------------------------------------------------------------------------
// tf32 tensor-core GEMM:  C[M,N] = A[M,K] @ W[N,K]^T  (row-major A and W)
// 128x128 block, BK=32, 256 threads (8 warps), warp tile 32x64 (mf2 x nf8).
// Double-buffered smem (ping-pong) + register-staged gmem prefetch:
// one __syncthreads per K-step. Optional fused RoPE on the output.
// ---------------------------------------------------------------------------
#define TST 36
#define GEMM_SMEM (2 * 2 * 128 * TST * 4)   // 73728 B dynamic

__global__ __launch_bounds__(256, 2) void sgemm_tf32(
    const float* __restrict__ A, const float* __restrict__ W,
    float* __restrict__ C, int M, int N, int K,
    const float* __restrict__ cosT, const float* __restrict__ sinT, int rope)
{
    extern __shared__ unsigned gsm[];
    unsigned* As = gsm;                 // [2][128*TST]
    unsigned* Bs = gsm + 2*128*TST;     // [2][128*TST]

    const int t    = threadIdx.x;
    const int wid  = t >> 5;
    const int lane = t & 31;
    const int grp  = lane >> 2;
    const int tig  = lane & 3;
    const int wm   = (wid >> 1) * 32;   // 4 row-warps
    const int wn   = (wid & 1) * 64;    // 2 col-warps

    const int lr0 = t >> 3;             // loader row base (0..31), +32 per chunk
    const int lc4 = (t & 7) * 4;        // loader col (0..28)

    const float* Ab = A + (size_t)(blockIdx.y * 128) * K;
    const float* Wb = W + (size_t)(blockIdx.x * 128) * K;

    float acc[2][8][4];
#pragma unroll
    for (int mf = 0; mf < 2; mf++)
#pragma unroll
        for (int nf = 0; nf < 8; nf++) {
            acc[mf][nf][0]=0.f; acc[mf][nf][1]=0.f;
            acc[mf][nf][2]=0.f; acc[mf][nf][3]=0.f;
        }

    // ---- preload tile k0=0 into buffer 0
    {
#pragma unroll
        for (int i = 0; i < 4; i++) {
            int r = lr0 + i*32;
            float4 av = *(const float4*)(Ab + (size_t)r * K + lc4);
            unsigned* ad = &As[r*TST + lc4];
            ad[0]=f2tf32(av.x); ad[1]=f2tf32(av.y); ad[2]=f2tf32(av.z); ad[3]=f2tf32(av.w);
        }
#pragma unroll
        for (int i = 0; i < 4; i++) {
            int r = lr0 + i*32;
            float4 bv = *(const float4*)(Wb + (size_t)r * K + lc4);
            unsigned* bd = &Bs[r*TST + lc4];
            bd[0]=f2tf32(bv.x); bd[1]=f2tf32(bv.y); bd[2]=f2tf32(bv.z); bd[3]=f2tf32(bv.w);
        }
    }
    __syncthreads();

    int buf = 0;
    for (int k0 = 0; k0 < K; k0 += 32) {
        const bool more = (k0 + 32 < K);
        const unsigned* Ac = As + buf*128*TST;
        const unsigned* Bc = Bs + buf*128*TST;
        unsigned* An = As + (buf^1)*128*TST;
        unsigned* Bn = Bs + (buf^1)*128*TST;

        // stage A for next tile
        float4 ra[4];
        if (more) {
#pragma unroll
            for (int i = 0; i < 4; i++)
                ra[i] = *(const float4*)(Ab + (size_t)(lr0 + i*32) * K + k0 + 32 + lc4);
        }

        // MMAs k8 = 0,1
#pragma unroll
        for (int k8 = 0; k8 < 2; k8++) {
            const int kb = k8 * 8;
            unsigned af[2][4];
#pragma unroll
            for (int mf = 0; mf < 2; mf++) {
                int mrow = wm + mf*16 + grp;
                af[mf][0] = Ac[(mrow  )*TST + kb + tig];
                af[mf][1] = Ac[(mrow+8)*TST + kb + tig];
                af[mf][2] = Ac[(mrow  )*TST + kb + tig + 4];
                af[mf][3] = Ac[(mrow+8)*TST + kb + tig + 4];
            }
#pragma unroll
            for (int nf = 0; nf < 8; nf++) {
                int n = wn + nf*8 + grp;
                unsigned b0 = Bc[n*TST + kb + tig];
                unsigned b1 = Bc[n*TST + kb + tig + 4];
#pragma unroll
                for (int mf = 0; mf < 2; mf++) {
                    float* c0 = &acc[mf][nf][0];
                    asm volatile(
                        "mma.sync.aligned.m16n8k8.row.col.f32.tf32.tf32.f32 "
                        "{%0,%1,%2,%3}, {%4,%5,%6,%7}, {%8,%9}, {%0,%1,%2,%3};"
                        : "+f"(c0[0]), "+f"(c0[1]), "+f"(c0[2]), "+f"(c0[3])
                        : "r"(af[mf][0]), "r"(af[mf][1]), "r"(af[mf][2]), "r"(af[mf][3]),
                          "r"(b0), "r"(b1));
                }
            }
        }

        // store staged A into next buffer, stage B
        float4 rb[4];
        if (more) {
#pragma unroll
            for (int i = 0; i < 4; i++) {
                int r = lr0 + i*32;
                unsigned* ad = &An[r*TST + lc4];
                ad[0]=f2tf32(ra[i].x); ad[1]=f2tf32(ra[i].y);
                ad[2]=f2tf32(ra[i].z); ad[3]=f2tf32(ra[i].w);
            }
#pragma unroll
            for (int i = 0; i < 4; i++)
                rb[i] = *(const float4*)(Wb + (size_t)(lr0 + i*32) * K + k0 + 32 + lc4);
        }

        // MMAs k8 = 2,3
#pragma unroll
        for (int k8 = 2; k8 < 4; k8++) {
            const int kb = k8 * 8;
            unsigned af[2][4];
#pragma unroll
            for (int mf = 0; mf < 2; mf++) {
                int mrow = wm + mf*16 + grp;
                af[mf][0] = Ac[(mrow  )*TST + kb + tig];
                af[mf][1] = Ac[(mrow+8)*TST + kb + tig];
                af[mf][2] = Ac[(mrow  )*TST + kb + tig + 4];
                af[mf][3] = Ac[(mrow+8)*TST + kb + tig + 4];
            }
#pragma unroll
            for (int nf = 0; nf < 8; nf++) {
                int n = wn + nf*8 + grp;
                unsigned b0 = Bc[n*TST + kb + tig];
                unsigned b1 = Bc[n*TST + kb + tig + 4];
#pragma unroll
                for (int mf = 0; mf < 2; mf++) {
                    float* c0 = &acc[mf][nf][0];
                    asm volatile(
                        "mma.sync.aligned.m16n8k8.row.col.f32.tf32.tf32.f32 "
                        "{%0,%1,%2,%3}, {%4,%5,%6,%7}, {%8,%9}, {%0,%1,%2,%3};"
                        : "+f"(c0[0]), "+f"(c0[1]), "+f"(c0[2]), "+f"(c0[3])
                        : "r"(af[mf][0]), "r"(af[mf][1]), "r"(af[mf][2]), "r"(af[mf][3]),
                          "r"(b0), "r"(b1));
                }
            }
        }

        if (more) {
#pragma unroll
            for (int i = 0; i < 4; i++) {
                int r = lr0 + i*32;
                unsigned* bd = &Bn[r*TST + lc4];
                bd[0]=f2tf32(rb[i].x); bd[1]=f2tf32(rb[i].y);
                bd[2]=f2tf32(rb[i].z); bd[3]=f2tf32(rb[i].w);
            }
            __syncthreads();
            buf ^= 1;
        }
    }

    // Optional fused RoPE: lo cols are nf<4 (i = nf*8+tig*2 < 32), hi = nf+4.
    if (rope) {
#pragma unroll
        for (int mf = 0; mf < 2; mf++) {
#pragma unroll
            for (int nf = 0; nf < 4; nf++) {
                const int i0 = nf*8 + tig*2;
#pragma unroll
                for (int hh = 0; hh < 2; hh++) {
                    int row = blockIdx.y*128 + wm + mf*16 + grp + hh*8;
                    int s   = row & (S_ - 1);
#pragma unroll
                    for (int j = 0; j < 2; j++) {
                        float c  = cosT[s*HD + i0 + j];
                        float sn = sinT[s*HD + i0 + j];
                        float L = acc[mf][nf  ][hh*2 + j];
                        float H = acc[mf][nf+4][hh*2 + j];
                        acc[mf][nf  ][hh*2 + j] = L*c - H*sn;
                        acc[mf][nf+4][hh*2 + j] = H*c + L*sn;
                    }
                }
            }
        }
    }

#pragma unroll
    for (int mf = 0; mf < 2; mf++) {
#pragma unroll
        for (int nf = 0; nf < 8; nf++) {
            float* c0 = &acc[mf][nf][0];
            int row = blockIdx.y*128 + wm + mf*16 + grp;
            int col = blockIdx.x*128 + wn + nf*8 + tig*2;
            *(float2*)(C + (size_t)row*N + col)     = make_float2(c0[0], c0[1]);
            *(float2*)(C + (size_t)(row+8)*N + col) = make_float2(c0[2], c0[3]);
        }
    }
}

// ---------------------------------------------------------------------------
// Tensor-core causal flash attention v4 (tf32 mma.sync.m16n8k8).
// grid (NH, S/128, B), 128 threads (4 warps). BM=128 (32 q-rows/warp, mf=2),
// BN=64. Q lives in SMEM (scaled by 1/8 at load) instead of 64 registers ->
// no spills. K/V/P in smem as in R5.
// ---------------------------------------------------------------------------
#define FST 68
#define FA_SMEM ((64*FST*2 + 128*FST*2) * 4)   // Ks+Vs+Ps+Qs = 104448 B

__global__ __launch_bounds__(128) void flash_attn_mma4(
    const float* __restrict__ Q, const float* __restrict__ K,
    const float* __restrict__ V, float* __restrict__ O)
{
    extern __shared__ unsigned fsm[];
    unsigned* Ks = fsm;              // [64][FST]
    unsigned* Vs = Ks + 64*FST;      // [64][FST]
    unsigned* Ps = Vs + 64*FST;      // [128][FST]
    unsigned* Qs = Ps + 128*FST;     // [128][FST]

    const int h  = blockIdx.x;
    const int bm = (gridDim.y - 1) - blockIdx.y;   // heaviest blocks first
    const int b  = blockIdx.z;
    const int hk = h >> 2;                          // GQA
    const int t    = threadIdx.x;
    const int w    = t >> 5;
    const int lane = t & 31;
    const int grp  = lane >> 2;
    const int tig  = lane & 3;
    const int rb   = bm*128 + w*32;   // warp's first q row (global)

    // ---- load Q tile into smem, pre-scaled by 1/8, tf32
#pragma unroll
    for (int i = 0; i < 16; i++) {
        int idx = t + i*128;
        int r   = idx >> 4;
        int c4  = (idx & 15) * 4;
        float4 qv = *(const float4*)(Q + (((size_t)(b*S_ + bm*128 + r)*NH + h) << 6) + c4);
        unsigned* qd = &Qs[r*FST + c4];
        qd[0]=f2tf32(0.125f*qv.x); qd[1]=f2tf32(0.125f*qv.y);
        qd[2]=f2tf32(0.125f*qv.z); qd[3]=f2tf32(0.125f*qv.w);
    }

    float oacc[2][8][4];
#pragma unroll
    for (int mf = 0; mf < 2; mf++)
#pragma unroll
        for (int nf = 0; nf < 8; nf++) {
            oacc[mf][nf][0]=0.f; oacc[mf][nf][1]=0.f;
            oacc[mf][nf][2]=0.f; oacc[mf][nf][3]=0.f;
        }
    float m[4]  = {-1e30f, -1e30f, -1e30f, -1e30f};
    float l[4]  = {0.f, 0.f, 0.f, 0.f};

    const int ntiles = 2*(bm + 1);
    for (int tile = 0; tile < ntiles; tile++) {
        __syncthreads();   // Ks/Vs reuse; first iter also covers Qs load
        // ---- load K,V tile (64 keys x 64 dims), convert to tf32
#pragma unroll
        for (int i = 0; i < 8; i++) {
            int idx = t + i*128;
            int r   = idx >> 4;
            int c4  = (idx & 15) * 4;
            size_t gb = (((size_t)(b*S_ + tile*64 + r)*NKV + hk) << 6) + c4;
            float4 kv = *(const float4*)(K + gb);
            float4 vv = *(const float4*)(V + gb);
            unsigned* kd = &Ks[r*FST + c4];
            kd[0]=f2tf32(kv.x); kd[1]=f2tf32(kv.y); kd[2]=f2tf32(kv.z); kd[3]=f2tf32(kv.w);
            unsigned* vd = &Vs[r*FST + c4];
            vd[0]=f2tf32(vv.x); vd[1]=f2tf32(vv.y); vd[2]=f2tf32(vv.z); vd[3]=f2tf32(vv.w);
        }
        __syncthreads();

        // ---- S = (Q/8) K^T : per warp 32x64
        float sacc[2][8][4];
#pragma unroll
        for (int mf = 0; mf < 2; mf++)
#pragma unroll
            for (int nf = 0; nf < 8; nf++) {
                sacc[mf][nf][0]=0.f; sacc[mf][nf][1]=0.f;
                sacc[mf][nf][2]=0.f; sacc[mf][nf][3]=0.f;
            }
#pragma unroll
        for (int kb = 0; kb < 8; kb++) {
            unsigned af[2][4];
#pragma unroll
            for (int mf = 0; mf < 2; mf++) {
                const int rr = (w*32 + mf*16 + grp)*FST + kb*8 + tig;
                af[mf][0] = Qs[rr];
                af[mf][1] = Qs[rr + 8*FST];
                af[mf][2] = Qs[rr + 4];
                af[mf][3] = Qs[rr + 8*FST + 4];
            }
#pragma unroll
            for (int nf = 0; nf < 8; nf++) {
                unsigned b0 = Ks[(nf*8+grp)*FST + kb*8 + tig];
                unsigned b1 = Ks[(nf*8+grp)*FST + kb*8 + tig + 4];
#pragma unroll
                for (int mf = 0; mf < 2; mf++) {
                    float* c0 = &sacc[mf][nf][0];
                    asm volatile(
                        "mma.sync.aligned.m16n8k8.row.col.f32.tf32.tf32.f32 "
                        "{%0,%1,%2,%3}, {%4,%5,%6,%7}, {%8,%9}, {%0,%1,%2,%3};"
                        : "+f"(c0[0]), "+f"(c0[1]), "+f"(c0[2]), "+f"(c0[3])
                        : "r"(af[mf][0]), "r"(af[mf][1]), "r"(af[mf][2]), "r"(af[mf][3]),
                          "r"(b0), "r"(b1));
                }
            }
        }

        // ---- online softmax on fragment layout
        const bool diag = (tile >= 2*bm);
        const int colb = tile*64;
#pragma unroll
        for (int mf = 0; mf < 2; mf++) {
            const int r0 = rb + mf*16 + grp;
            const int r1 = r0 + 8;
            float mt0 = -1e30f, mt1 = -1e30f;
#pragma unroll
            for (int nf = 0; nf < 8; nf++) {
                const int c0i = colb + nf*8 + tig*2;
                if (diag) {
                    if (c0i     > r0) sacc[mf][nf][0] = -1e30f;
                    if (c0i + 1 > r0) sacc[mf][nf][1] = -1e30f;
                    if (c0i     > r1) sacc[mf][nf][2] = -1e30f;
                    if (c0i + 1 > r1) sacc[mf][nf][3] = -1e30f;
                }
                mt0 = fmaxf(mt0, fmaxf(sacc[mf][nf][0], sacc[mf][nf][1]));
                mt1 = fmaxf(mt1, fmaxf(sacc[mf][nf][2], sacc[mf][nf][3]));
            }
            mt0 = fmaxf(mt0, __shfl_xor_sync(0xffffffffu, mt0, 1));
            mt0 = fmaxf(mt0, __shfl_xor_sync(0xffffffffu, mt0, 2));
            mt1 = fmaxf(mt1, __shfl_xor_sync(0xffffffffu, mt1, 1));
            mt1 = fmaxf(mt1, __shfl_xor_sync(0xffffffffu, mt1, 2));

            const float mn0 = fmaxf(m[mf*2  ], mt0);
            const float mn1 = fmaxf(m[mf*2+1], mt1);
            const float cr0 = __expf(m[mf*2  ] - mn0);
            const float cr1 = __expf(m[mf*2+1] - mn1);
            float ps0 = 0.f, ps1 = 0.f;

            unsigned* P0 = &Ps[(w*32 + mf*16 + grp)*FST + tig*2];
            unsigned* P1 = P0 + 8*FST;
#pragma unroll
            for (int nf = 0; nf < 8; nf++) {
                float p00 = __expf(sacc[mf][nf][0] - mn0);
                float p01 = __expf(sacc[mf][nf][1] - mn0);
                float p10 = __expf(sacc[mf][nf][2] - mn1);
                float p11 = __expf(sacc[mf][nf][3] - mn1);
                ps0 += p00 + p01;
                ps1 += p10 + p11;
                *(uint2*)(P0 + nf*8) = make_uint2(f2tf32(p00), f2tf32(p01));
                *(uint2*)(P1 + nf*8) = make_uint2(f2tf32(p10), f2tf32(p11));
            }
            ps0 += __shfl_xor_sync(0xffffffffu, ps0, 1);
            ps0 += __shfl_xor_sync(0xffffffffu, ps0, 2);
            ps1 += __shfl_xor_sync(0xffffffffu, ps1, 1);
            ps1 += __shfl_xor_sync(0xffffffffu, ps1, 2);
            l[mf*2  ] = l[mf*2  ]*cr0 + ps0;  m[mf*2  ] = mn0;
            l[mf*2+1] = l[mf*2+1]*cr1 + ps1;  m[mf*2+1] = mn1;
#pragma unroll
            for (int nf = 0; nf < 8; nf++) {
                oacc[mf][nf][0] *= cr0; oacc[mf][nf][1] *= cr0;
                oacc[mf][nf][2] *= cr1; oacc[mf][nf][3] *= cr1;
            }
        }
        __syncwarp();   // Ps region is warp-private

        // ---- O += P V
#pragma unroll
        for (int kb = 0; kb < 8; kb++) {
            unsigned a[2][4];
#pragma unroll
            for (int mf = 0; mf < 2; mf++) {
                const int pr = w*32 + mf*16 + grp;
                a[mf][0] = Ps[(pr    )*FST + kb*8 + tig];
                a[mf][1] = Ps[(pr + 8)*FST + kb*8 + tig];
                a[mf][2] = Ps[(pr    )*FST + kb*8 + tig + 4];
                a[mf][3] = Ps[(pr + 8)*FST + kb*8 + tig + 4];
            }
#pragma unroll
            for (int nf = 0; nf < 8; nf++) {
                unsigned b0 = Vs[(kb*8 + tig    )*FST + nf*8 + grp];
                unsigned b1 = Vs[(kb*8 + tig + 4)*FST + nf*8 + grp];
#pragma unroll
                for (int mf = 0; mf < 2; mf++) {
                    float* c0 = &oacc[mf][nf][0];
                    asm volatile(
                        "mma.sync.aligned.m16n8k8.row.col.f32.tf32.tf32.f32 "
                        "{%0,%1,%2,%3}, {%4,%5,%6,%7}, {%8,%9}, {%0,%1,%2,%3};"
                        : "+f"(c0[0]), "+f"(c0[1]), "+f"(c0[2]), "+f"(c0[3])
                        : "r"(a[mf][0]), "r"(a[mf][1]), "r"(a[mf][2]), "r"(a[mf][3]),
                          "r"(b0), "r"(b1));
                }
            }
        }
    }

    // ---- epilogue: O / l
#pragma unroll
    for (int mf = 0; mf < 2; mf++) {
        const float inv0 = 1.f / l[mf*2];
        const float inv1 = 1.f / l[mf*2+1];
        float* o0 = O + (((size_t)(b*S_ + rb + mf*16 + grp    )*NH + h) << 6) + tig*2;
        float* o1 = O + (((size_t)(b*S_ + rb + mf*16 + grp + 8)*NH + h) << 6) + tig*2;
#pragma unroll
        for (int nf = 0; nf < 8; nf++) {
            *(float2*)(o0 + nf*8) = make_float2(oacc[mf][nf][0]*inv0, oacc[mf][nf][1]*inv0);
            *(float2*)(o1 + nf*8) = make_float2(oacc[mf][nf][2]*inv1, oacc[mf][nf][3]*inv1);
        }
    }
}

// ---------------------------------------------------------------------------
extern "C" void kernel_launch(void* const* d_in, const int* in_sizes, int n_in,
                              void* d_out, int out_size)
{
    const float* x    = (const float*)d_in[0];
    const float* cosT = (const float*)d_in[1];
    const float* sinT = (const float*)d_in[2];
    const float* wq   = (const float*)d_in[3];
    const float* wk   = (const float*)d_in[4];
    const float* wv   = (const float*)d_in[5];
    const float* wo   = (const float*)d_in[6];
    float* out = (float*)d_out;

    float *Q, *K, *V, *Aat;
    cudaGetSymbolAddress((void**)&Q,   g_Q);
    cudaGetSymbolAddress((void**)&K,   g_K);
    cudaGetSymbolAddress((void**)&V,   g_V);
    cudaGetSymbolAddress((void**)&Aat, g_A);

    static bool attr_set = false;
    if (!attr_set) {
        cudaFuncSetAttribute(sgemm_tf32, cudaFuncAttributeMaxDynamicSharedMemorySize, GEMM_SMEM);
        cudaFuncSetAttribute(flash_attn_mma4, cudaFuncAttributeMaxDynamicSharedMemorySize, FA_SMEM);
        attr_set = true;
    }

    // Projections (tf32 tensor cores); RoPE fused into Q/K epilogues
    sgemm_tf32<<<dim3(HID/128,       MROWS/128), 256, GEMM_SMEM>>>(x, wq, Q, MROWS, HID,    HID, cosT, sinT, 1);
    sgemm_tf32<<<dim3((NKV*HD)/128,  MROWS/128), 256, GEMM_SMEM>>>(x, wk, K, MROWS, NKV*HD, HID, cosT, sinT, 1);
    sgemm_tf32<<<dim3((NKV*HD)/128,  MROWS/128), 256, GEMM_SMEM>>>(x, wv, V, MROWS, NKV*HD, HID, cosT, sinT, 0);

    // Tensor-core causal GQA flash attention
    flash_attn_mma4<<<dim3(NH, S_/128, B_), 128, FA_SMEM>>>(Q, K, V, Aat);

    // Output projection (tf32 tensor cores)
    sgemm_tf32<<<dim3(HID/128, MROWS/128), 256, GEMM_SMEM>>>(Aat, wo, out, MROWS, HID, HID, cosT, sinT, 0);
}

// round 8
// speedup vs baseline: 1.1757x; 1.1757x over previous
#include <cuda_runtime.h>
#include <math.h>

#define B_  2
#define S_  2048
#define HID 1024
#define NH  16
#define NKV 4
#define HD  64
#define MROWS (B_*S_)   // 4096

// Scratch (no cudaMalloc allowed)
__device__ float g_Q[MROWS * HID];        // [B,S,NH,HD]
__device__ float g_K[MROWS * NKV * HD];   // [B,S,NKV,HD]
__device__ float g_V[MROWS * NKV * HD];
__device__ float g_A[MROWS * HID];        // attention output [B,S,NH,HD]

__device__ __forceinline__ unsigned f2tf32(float x) {
    unsigned r;
    asm("cvt.rna.tf32.f32 %0, %1;" : "=r"(r) : "f"(x));
    return r;
}

// ---------------------------------------------------------------------------
// tf32 tensor-core GEMM (mma.sync m16n8k8): C[M,N] = A[M,K] @ W[N,K]^T.
// 128x128 block, BK=32, 256 threads (8 warps), warp tile 32x64 (mf2 x nf8).
// Double-buffered ping-pong smem + register-staged prefetch, ONE sync/K-step.
// No min-blocks clause -> no register cap -> no spills (R6 lesson).
// Dual-output mode: block-columns [0,nx1) compute W1->C1 (rope1),
// columns [nx1,gridDim.x) compute W2->C2 (rope2). Lets K and V projections
// share one launch for full SM coverage.
// ---------------------------------------------------------------------------
#define TST 36
#define GEMM_SMEM (2 * 2 * 128 * TST * 4)   // 73728 B dynamic

__global__ __launch_bounds__(256) void sgemm_tf32(
    const float* __restrict__ A,
    const float* __restrict__ W1, float* __restrict__ C1, int nx1, int rope1,
    const float* __restrict__ W2, float* __restrict__ C2, int rope2,
    int M, int N, int K,
    const float* __restrict__ cosT, const float* __restrict__ sinT)
{
    extern __shared__ unsigned gsm[];
    unsigned* As = gsm;                 // [2][128*TST]
    unsigned* Bs = gsm + 2*128*TST;     // [2][128*TST]

    int bx = blockIdx.x;
    const float* W; float* C; int rope;
    if (bx < nx1) { W = W1; C = C1; rope = rope1; }
    else          { W = W2; C = C2; rope = rope2; bx -= nx1; }

    const int t    = threadIdx.x;
    const int wid  = t >> 5;
    const int lane = t & 31;
    const int grp  = lane >> 2;
    const int tig  = lane & 3;
    const int wm   = (wid >> 1) * 32;   // 4 row-warps
    const int wn   = (wid & 1) * 64;    // 2 col-warps

    const int lr0 = t >> 3;             // loader row base (0..31), +32 per chunk
    const int lc4 = (t & 7) * 4;        // loader col (0..28)

    const float* Ab = A + (size_t)(blockIdx.y * 128) * K;
    const float* Wb = W + (size_t)(bx * 128) * K;

    float acc[2][8][4];
#pragma unroll
    for (int mf = 0; mf < 2; mf++)
#pragma unroll
        for (int nf = 0; nf < 8; nf++) {
            acc[mf][nf][0]=0.f; acc[mf][nf][1]=0.f;
            acc[mf][nf][2]=0.f; acc[mf][nf][3]=0.f;
        }

    // ---- preload tile k0=0 into buffer 0
#pragma unroll
    for (int i = 0; i < 4; i++) {
        int r = lr0 + i*32;
        float4 av = *(const float4*)(Ab + (size_t)r * K + lc4);
        unsigned* ad = &As[r*TST + lc4];
        ad[0]=f2tf32(av.x); ad[1]=f2tf32(av.y); ad[2]=f2tf32(av.z); ad[3]=f2tf32(av.w);
    }
#pragma unroll
    for (int i = 0; i < 4; i++) {
        int r = lr0 + i*32;
        float4 bv = *(const float4*)(Wb + (size_t)r * K + lc4);
        unsigned* bd = &Bs[r*TST + lc4];
        bd[0]=f2tf32(bv.x); bd[1]=f2tf32(bv.y); bd[2]=f2tf32(bv.z); bd[3]=f2tf32(bv.w);
    }
    __syncthreads();

    int buf = 0;
    for (int k0 = 0; k0 < K; k0 += 32) {
        const bool more = (k0 + 32 < K);
        const unsigned* Ac = As + buf*128*TST;
        const unsigned* Bc = Bs + buf*128*TST;
        unsigned* An = As + (buf^1)*128*TST;
        unsigned* Bn = Bs + (buf^1)*128*TST;

        // stage A for next tile
        float4 ra[4];
        if (more) {
#pragma unroll
            for (int i = 0; i < 4; i++)
                ra[i] = *(const float4*)(Ab + (size_t)(lr0 + i*32) * K + k0 + 32 + lc4);
        }

        // MMAs k8 = 0,1
#pragma unroll
        for (int k8 = 0; k8 < 2; k8++) {
            const int kb = k8 * 8;
            unsigned af[2][4];
#pragma unroll
            for (int mf = 0; mf < 2; mf++) {
                int mrow = wm + mf*16 + grp;
                af[mf][0] = Ac[(mrow  )*TST + kb + tig];
                af[mf][1] = Ac[(mrow+8)*TST + kb + tig];
                af[mf][2] = Ac[(mrow  )*TST + kb + tig + 4];
                af[mf][3] = Ac[(mrow+8)*TST + kb + tig + 4];
            }
#pragma unroll
            for (int nf = 0; nf < 8; nf++) {
                int n = wn + nf*8 + grp;
                unsigned b0 = Bc[n*TST + kb + tig];
                unsigned b1 = Bc[n*TST + kb + tig + 4];
#pragma unroll
                for (int mf = 0; mf < 2; mf++) {
                    float* c0 = &acc[mf][nf][0];
                    asm volatile(
                        "mma.sync.aligned.m16n8k8.row.col.f32.tf32.tf32.f32 "
                        "{%0,%1,%2,%3}, {%4,%5,%6,%7}, {%8,%9}, {%0,%1,%2,%3};"
                        : "+f"(c0[0]), "+f"(c0[1]), "+f"(c0[2]), "+f"(c0[3])
                        : "r"(af[mf][0]), "r"(af[mf][1]), "r"(af[mf][2]), "r"(af[mf][3]),
                          "r"(b0), "r"(b1));
                }
            }
        }

        // store staged A into next buffer, stage B
        float4 rb[4];
        if (more) {
#pragma unroll
            for (int i = 0; i < 4; i++) {
                int r = lr0 + i*32;
                unsigned* ad = &An[r*TST + lc4];
                ad[0]=f2tf32(ra[i].x); ad[1]=f2tf32(ra[i].y);
                ad[2]=f2tf32(ra[i].z); ad[3]=f2tf32(ra[i].w);
            }
#pragma unroll
            for (int i = 0; i < 4; i++)
                rb[i] = *(const float4*)(Wb + (size_t)(lr0 + i*32) * K + k0 + 32 + lc4);
        }

        // MMAs k8 = 2,3
#pragma unroll
        for (int k8 = 2; k8 < 4; k8++) {
            const int kb = k8 * 8;
            unsigned af[2][4];
#pragma unroll
            for (int mf = 0; mf < 2; mf++) {
                int mrow = wm + mf*16 + grp;
                af[mf][0] = Ac[(mrow  )*TST + kb + tig];
                af[mf][1] = Ac[(mrow+8)*TST + kb + tig];
                af[mf][2] = Ac[(mrow  )*TST + kb + tig + 4];
                af[mf][3] = Ac[(mrow+8)*TST + kb + tig + 4];
            }
#pragma unroll
            for (int nf = 0; nf < 8; nf++) {
                int n = wn + nf*8 + grp;
                unsigned b0 = Bc[n*TST + kb + tig];
                unsigned b1 = Bc[n*TST + kb + tig + 4];
#pragma unroll
                for (int mf = 0; mf < 2; mf++) {
                    float* c0 = &acc[mf][nf][0];
                    asm volatile(
                        "mma.sync.aligned.m16n8k8.row.col.f32.tf32.tf32.f32 "
                        "{%0,%1,%2,%3}, {%4,%5,%6,%7}, {%8,%9}, {%0,%1,%2,%3};"
                        : "+f"(c0[0]), "+f"(c0[1]), "+f"(c0[2]), "+f"(c0[3])
                        : "r"(af[mf][0]), "r"(af[mf][1]), "r"(af[mf][2]), "r"(af[mf][3]),
                          "r"(b0), "r"(b1));
                }
            }
        }

        if (more) {
#pragma unroll
            for (int i = 0; i < 4; i++) {
                int r = lr0 + i*32;
                unsigned* bd = &Bn[r*TST + lc4];
                bd[0]=f2tf32(rb[i].x); bd[1]=f2tf32(rb[i].y);
                bd[2]=f2tf32(rb[i].z); bd[3]=f2tf32(rb[i].w);
            }
            __syncthreads();
            buf ^= 1;
        }
    }

    // Optional fused RoPE: lo cols are nf<4 (i = nf*8+tig*2 < 32), hi = nf+4.
    if (rope) {
#pragma unroll
        for (int mf = 0; mf < 2; mf++) {
#pragma unroll
            for (int nf = 0; nf < 4; nf++) {
                const int i0 = nf*8 + tig*2;
#pragma unroll
                for (int hh = 0; hh < 2; hh++) {
                    int row = blockIdx.y*128 + wm + mf*16 + grp + hh*8;
                    int s   = row & (S_ - 1);
#pragma unroll
                    for (int j = 0; j < 2; j++) {
                        float c  = cosT[s*HD + i0 + j];
                        float sn = sinT[s*HD + i0 + j];
                        float L = acc[mf][nf  ][hh*2 + j];
                        float H = acc[mf][nf+4][hh*2 + j];
                        acc[mf][nf  ][hh*2 + j] = L*c - H*sn;
                        acc[mf][nf+4][hh*2 + j] = H*c + L*sn;
                    }
                }
            }
        }
    }

#pragma unroll
    for (int mf = 0; mf < 2; mf++) {
#pragma unroll
        for (int nf = 0; nf < 8; nf++) {
            float* c0 = &acc[mf][nf][0];
            int row = blockIdx.y*128 + wm + mf*16 + grp;
            int col = bx*128 + wn + nf*8 + tig*2;
            *(float2*)(C + (size_t)row*N + col)     = make_float2(c0[0], c0[1]);
            *(float2*)(C + (size_t)(row+8)*N + col) = make_float2(c0[2], c0[3]);
        }
    }
}

// ---------------------------------------------------------------------------
// Tensor-core causal flash attention v3 (tf32 mma.sync) -- the R5 version,
// measured fastest (155.5us). 128 threads, BM=128, BN=64, Q in registers.
// ---------------------------------------------------------------------------
#define FST 68
#define FA_SMEM ((64*FST*2 + 128*FST) * 4)   // Ks + Vs + Ps = 69632 B

__global__ __launch_bounds__(128) void flash_attn_mma3(
    const float* __restrict__ Q, const float* __restrict__ K,
    const float* __restrict__ V, float* __restrict__ O)
{
    extern __shared__ unsigned fsm[];
    unsigned* Ks = fsm;              // [64][FST]
    unsigned* Vs = Ks + 64*FST;      // [64][FST]
    unsigned* Ps = Vs + 64*FST;      // [128][FST]

    const int h  = blockIdx.x;
    const int bm = (gridDim.y - 1) - blockIdx.y;   // heaviest blocks first
    const int b  = blockIdx.z;
    const int hk = h >> 2;                          // GQA
    const int t    = threadIdx.x;
    const int w    = t >> 5;
    const int lane = t & 31;
    const int grp  = lane >> 2;
    const int tig  = lane & 3;
    const int rb   = bm*128 + w*32;   // warp's first q row (global)

    // ---- Q fragments: 2 mf x 8 kb x 4 regs, scaled by 1/8, tf32
    unsigned qf[2][8][4];
#pragma unroll
    for (int mf = 0; mf < 2; mf++) {
        const float* q0 = Q + (((size_t)(b*S_ + rb + mf*16 + grp    )*NH + h) << 6);
        const float* q1 = Q + (((size_t)(b*S_ + rb + mf*16 + grp + 8)*NH + h) << 6);
#pragma unroll
        for (int kb = 0; kb < 8; kb++) {
            qf[mf][kb][0] = f2tf32(0.125f * q0[kb*8 + tig]);
            qf[mf][kb][1] = f2tf32(0.125f * q1[kb*8 + tig]);
            qf[mf][kb][2] = f2tf32(0.125f * q0[kb*8 + tig + 4]);
            qf[mf][kb][3] = f2tf32(0.125f * q1[kb*8 + tig + 4]);
        }
    }

    float oacc[2][8][4];
#pragma unroll
    for (int mf = 0; mf < 2; mf++)
#pragma unroll
        for (int nf = 0; nf < 8; nf++) {
            oacc[mf][nf][0]=0.f; oacc[mf][nf][1]=0.f;
            oacc[mf][nf][2]=0.f; oacc[mf][nf][3]=0.f;
        }
    float m[4]  = {-1e30f, -1e30f, -1e30f, -1e30f};
    float l[4]  = {0.f, 0.f, 0.f, 0.f};

    const int ntiles = 2*(bm + 1);
    for (int tile = 0; tile < ntiles; tile++) {
        __syncthreads();
        // ---- load K,V tile (64 keys x 64 dims), convert to tf32
#pragma unroll
        for (int i = 0; i < 8; i++) {
            int idx = t + i*128;
            int r   = idx >> 4;
            int c4  = (idx & 15) * 4;
            size_t gb = (((size_t)(b*S_ + tile*64 + r)*NKV + hk) << 6) + c4;
            float4 kv = *(const float4*)(K + gb);
            float4 vv = *(const float4*)(V + gb);
            unsigned* kd = &Ks[r*FST + c4];
            kd[0]=f2tf32(kv.x); kd[1]=f2tf32(kv.y); kd[2]=f2tf32(kv.z); kd[3]=f2tf32(kv.w);
            unsigned* vd = &Vs[r*FST + c4];
            vd[0]=f2tf32(vv.x); vd[1]=f2tf32(vv.y); vd[2]=f2tf32(vv.z); vd[3]=f2tf32(vv.w);
        }
        __syncthreads();

        // ---- S = (Q/8) K^T : per warp 32x64
        float sacc[2][8][4];
#pragma unroll
        for (int mf = 0; mf < 2; mf++)
#pragma unroll
            for (int nf = 0; nf < 8; nf++) {
                sacc[mf][nf][0]=0.f; sacc[mf][nf][1]=0.f;
                sacc[mf][nf][2]=0.f; sacc[mf][nf][3]=0.f;
            }
#pragma unroll
        for (int kb = 0; kb < 8; kb++) {
#pragma unroll
            for (int nf = 0; nf < 8; nf++) {
                unsigned b0 = Ks[(nf*8+grp)*FST + kb*8 + tig];
                unsigned b1 = Ks[(nf*8+grp)*FST + kb*8 + tig + 4];
#pragma unroll
                for (int mf = 0; mf < 2; mf++) {
                    float* c0 = &sacc[mf][nf][0];
                    asm volatile(
                        "mma.sync.aligned.m16n8k8.row.col.f32.tf32.tf32.f32 "
                        "{%0,%1,%2,%3}, {%4,%5,%6,%7}, {%8,%9}, {%0,%1,%2,%3};"
                        : "+f"(c0[0]), "+f"(c0[1]), "+f"(c0[2]), "+f"(c0[3])
                        : "r"(qf[mf][kb][0]), "r"(qf[mf][kb][1]),
                          "r"(qf[mf][kb][2]), "r"(qf[mf][kb][3]),
                          "r"(b0), "r"(b1));
                }
            }
        }

        // ---- online softmax on fragment layout
        const bool diag = (tile >= 2*bm);
        const int colb = tile*64;
#pragma unroll
        for (int mf = 0; mf < 2; mf++) {
            const int r0 = rb + mf*16 + grp;
            const int r1 = r0 + 8;
            float mt0 = -1e30f, mt1 = -1e30f;
#pragma unroll
            for (int nf = 0; nf < 8; nf++) {
                const int c0i = colb + nf*8 + tig*2;
                if (diag) {
                    if (c0i     > r0) sacc[mf][nf][0] = -1e30f;
                    if (c0i + 1 > r0) sacc[mf][nf][1] = -1e30f;
                    if (c0i     > r1) sacc[mf][nf][2] = -1e30f;
                    if (c0i + 1 > r1) sacc[mf][nf][3] = -1e30f;
                }
                mt0 = fmaxf(mt0, fmaxf(sacc[mf][nf][0], sacc[mf][nf][1]));
                mt1 = fmaxf(mt1, fmaxf(sacc[mf][nf][2], sacc[mf][nf][3]));
            }
            mt0 = fmaxf(mt0, __shfl_xor_sync(0xffffffffu, mt0, 1));
            mt0 = fmaxf(mt0, __shfl_xor_sync(0xffffffffu, mt0, 2));
            mt1 = fmaxf(mt1, __shfl_xor_sync(0xffffffffu, mt1, 1));
            mt1 = fmaxf(mt1, __shfl_xor_sync(0xffffffffu, mt1, 2));

            const float mn0 = fmaxf(m[mf*2  ], mt0);
            const float mn1 = fmaxf(m[mf*2+1], mt1);
            const float cr0 = __expf(m[mf*2  ] - mn0);
            const float cr1 = __expf(m[mf*2+1] - mn1);
            float ps0 = 0.f, ps1 = 0.f;

            unsigned* P0 = &Ps[(w*32 + mf*16 + grp)*FST + tig*2];
            unsigned* P1 = P0 + 8*FST;
#pragma unroll
            for (int nf = 0; nf < 8; nf++) {
                float p00 = __expf(sacc[mf][nf][0] - mn0);
                float p01 = __expf(sacc[mf][nf][1] - mn0);
                float p10 = __expf(sacc[mf][nf][2] - mn1);
                float p11 = __expf(sacc[mf][nf][3] - mn1);
                ps0 += p00 + p01;
                ps1 += p10 + p11;
                *(uint2*)(P0 + nf*8) = make_uint2(f2tf32(p00), f2tf32(p01));
                *(uint2*)(P1 + nf*8) = make_uint2(f2tf32(p10), f2tf32(p11));
            }
            ps0 += __shfl_xor_sync(0xffffffffu, ps0, 1);
            ps0 += __shfl_xor_sync(0xffffffffu, ps0, 2);
            ps1 += __shfl_xor_sync(0xffffffffu, ps1, 1);
            ps1 += __shfl_xor_sync(0xffffffffu, ps1, 2);
            l[mf*2  ] = l[mf*2  ]*cr0 + ps0;  m[mf*2  ] = mn0;
            l[mf*2+1] = l[mf*2+1]*cr1 + ps1;  m[mf*2+1] = mn1;
#pragma unroll
            for (int nf = 0; nf < 8; nf++) {
                oacc[mf][nf][0] *= cr0; oacc[mf][nf][1] *= cr0;
                oacc[mf][nf][2] *= cr1; oacc[mf][nf][3] *= cr1;
            }
        }
        __syncwarp();   // Ps region is warp-private

        // ---- O += P V
#pragma unroll
        for (int kb = 0; kb < 8; kb++) {
            unsigned a[2][4];
#pragma unroll
            for (int mf = 0; mf < 2; mf++) {
                const int pr = w*32 + mf*16 + grp;
                a[mf][0] = Ps[(pr    )*FST + kb*8 + tig];
                a[mf][1] = Ps[(pr + 8)*FST + kb*8 + tig];
                a[mf][2] = Ps[(pr    )*FST + kb*8 + tig + 4];
                a[mf][3] = Ps[(pr + 8)*FST + kb*8 + tig + 4];
            }
#pragma unroll
            for (int nf = 0; nf < 8; nf++) {
                unsigned b0 = Vs[(kb*8 + tig    )*FST + nf*8 + grp];
                unsigned b1 = Vs[(kb*8 + tig + 4)*FST + nf*8 + grp];
#pragma unroll
                for (int mf = 0; mf < 2; mf++) {
                    float* c0 = &oacc[mf][nf][0];
                    asm volatile(
                        "mma.sync.aligned.m16n8k8.row.col.f32.tf32.tf32.f32 "
                        "{%0,%1,%2,%3}, {%4,%5,%6,%7}, {%8,%9}, {%0,%1,%2,%3};"
                        : "+f"(c0[0]), "+f"(c0[1]), "+f"(c0[2]), "+f"(c0[3])
                        : "r"(a[mf][0]), "r"(a[mf][1]), "r"(a[mf][2]), "r"(a[mf][3]),
                          "r"(b0), "r"(b1));
                }
            }
        }
    }

    // ---- epilogue: O / l
#pragma unroll
    for (int mf = 0; mf < 2; mf++) {
        const float inv0 = 1.f / l[mf*2];
        const float inv1 = 1.f / l[mf*2+1];
        float* o0 = O + (((size_t)(b*S_ + rb + mf*16 + grp    )*NH + h) << 6) + tig*2;
        float* o1 = O + (((size_t)(b*S_ + rb + mf*16 + grp + 8)*NH + h) << 6) + tig*2;
#pragma unroll
        for (int nf = 0; nf < 8; nf++) {
            *(float2*)(o0 + nf*8) = make_float2(oacc[mf][nf][0]*inv0, oacc[mf][nf][1]*inv0);
            *(float2*)(o1 + nf*8) = make_float2(oacc[mf][nf][2]*inv1, oacc[mf][nf][3]*inv1);
        }
    }
}

// ---------------------------------------------------------------------------
extern "C" void kernel_launch(void* const* d_in, const int* in_sizes, int n_in,
                              void* d_out, int out_size)
{
    const float* x    = (const float*)d_in[0];
    const float* cosT = (const float*)d_in[1];
    const float* sinT = (const float*)d_in[2];
    const float* wq   = (const float*)d_in[3];
    const float* wk   = (const float*)d_in[4];
    const float* wv   = (const float*)d_in[5];
    const float* wo   = (const float*)d_in[6];
    float* out = (float*)d_out;

    float *Q, *K, *V, *Aat;
    cudaGetSymbolAddress((void**)&Q,   g_Q);
    cudaGetSymbolAddress((void**)&K,   g_K);
    cudaGetSymbolAddress((void**)&V,   g_V);
    cudaGetSymbolAddress((void**)&Aat, g_A);

    static bool attr_set = false;
    if (!attr_set) {
        cudaFuncSetAttribute(sgemm_tf32, cudaFuncAttributeMaxDynamicSharedMemorySize, GEMM_SMEM);
        cudaFuncSetAttribute(flash_attn_mma3, cudaFuncAttributeMaxDynamicSharedMemorySize, FA_SMEM);
        attr_set = true;
    }

    // Q projection (rope fused)
    sgemm_tf32<<<dim3(HID/128, MROWS/128), 256, GEMM_SMEM>>>(
        x, wq, Q, HID/128, 1, nullptr, nullptr, 0,
        MROWS, HID, HID, cosT, sinT);

    // K (rope) + V projections merged into one launch: grid.x = 2 + 2
    sgemm_tf32<<<dim3(2*(NKV*HD)/128, MROWS/128), 256, GEMM_SMEM>>>(
        x, wk, K, (NKV*HD)/128, 1, wv, V, 0,
        MROWS, NKV*HD, HID, cosT, sinT);

    // Tensor-core causal GQA flash attention
    flash_attn_mma3<<<dim3(NH, S_/128, B_), 128, FA_SMEM>>>(Q, K, V, Aat);

    // Output projection
    sgemm_tf32<<<dim3(HID/128, MROWS/128), 256, GEMM_SMEM>>>(
        Aat, wo, out, HID/128, 0, nullptr, nullptr, 0,
        MROWS, HID, HID, cosT, sinT);
}